// round 1
// baseline (speedup 1.0000x reference)
#include <cuda_runtime.h>
#include <cstdint>

#define N_ROWS 16384
#define DDIM   512
#define K_CODES 8192

#define BM 64
#define BN 128
#define BD 16

// scratch (no cudaMalloc allowed)
__device__ float  g_snorm[N_ROWS];
__device__ float  g_cnorm[K_CODES];
__device__ int    g_idx[N_ROWS];
__device__ double g_loss;

// ---------------------------------------------------------------------------
// Kernel 1: row norms for x (s[n] = sum z^2) and codebook (cn[k] = sum c^2).
// One warp per row. Also zeroes the loss accumulator (deterministic replay).
// ---------------------------------------------------------------------------
__global__ void rownorm_kernel(const float* __restrict__ x,
                               const float* __restrict__ cb) {
    if (blockIdx.x == 0 && threadIdx.x == 0) g_loss = 0.0;
    int warp = (blockIdx.x * blockDim.x + threadIdx.x) >> 5;
    int lane = threadIdx.x & 31;
    const int total = N_ROWS + K_CODES;
    if (warp >= total) return;
    const float* base = (warp < N_ROWS)
        ? x  + (size_t)warp * DDIM
        : cb + (size_t)(warp - N_ROWS) * DDIM;
    float s = 0.f;
#pragma unroll
    for (int i = 0; i < DDIM / 32; i++) {
        float v = base[lane + i * 32];
        s += v * v;
    }
#pragma unroll
    for (int o = 16; o; o >>= 1) s += __shfl_down_sync(0xffffffff, s, o);
    if (lane == 0) {
        if (warp < N_ROWS) g_snorm[warp] = s;
        else               g_cnorm[warp - N_ROWS] = s;
    }
}

// ---------------------------------------------------------------------------
// Kernel 2: fused distance GEMM + argmin.
// Block = 64 rows; sweeps all 8192 codes in tiles of 128.
// dist = fp32(fp32(s - 2*t) + cn), strict < argmin (lowest index on ties),
// exactly mirroring the reference expression's rounding structure.
// ---------------------------------------------------------------------------
__global__ void __launch_bounds__(256)
vq_argmin_kernel(const float* __restrict__ x, const float* __restrict__ cb) {
    __shared__ float xs[BD][BM + 4];
    __shared__ float cs[BD][BN + 4];
    __shared__ float s_sm[BM];
    __shared__ float cn_sm[BN];
    __shared__ float best_d[BM];
    __shared__ int   best_i[BM];
    __shared__ float red_d[BM * 16];
    __shared__ int   red_i[BM * 16];

    const int tid = threadIdx.x;
    const int tx  = tid & 15;   // code group  (8 codes)
    const int ty  = tid >> 4;   // row group   (4 rows)
    const int row0 = blockIdx.x * BM;

    if (tid < BM) {
        s_sm[tid]   = g_snorm[row0 + tid];
        best_d[tid] = 3.4e38f;
        best_i[tid] = 0;
    }

    for (int kt = 0; kt < K_CODES; kt += BN) {
        if (tid < BN) cn_sm[tid] = g_cnorm[kt + tid];

        float acc[4][8];
#pragma unroll
        for (int r = 0; r < 4; r++)
#pragma unroll
            for (int c = 0; c < 8; c++) acc[r][c] = 0.f;

        for (int dt = 0; dt < DDIM; dt += BD) {
            __syncthreads();
#pragma unroll
            for (int i = tid; i < BM * BD; i += 256) {
                int r = i >> 4, dd = i & 15;
                xs[dd][r] = x[(size_t)(row0 + r) * DDIM + dt + dd];
            }
#pragma unroll
            for (int i = tid; i < BN * BD; i += 256) {
                int kk = i >> 4, dd = i & 15;
                cs[dd][kk] = cb[(size_t)(kt + kk) * DDIM + dt + dd];
            }
            __syncthreads();
#pragma unroll
            for (int dd = 0; dd < BD; dd++) {
                float4 a  = *(const float4*)&xs[dd][ty * 4];
                float4 b0 = *(const float4*)&cs[dd][tx * 8];
                float4 b1 = *(const float4*)&cs[dd][tx * 8 + 4];
                float ar[4] = {a.x, a.y, a.z, a.w};
                float br[8] = {b0.x, b0.y, b0.z, b0.w, b1.x, b1.y, b1.z, b1.w};
#pragma unroll
                for (int r = 0; r < 4; r++)
#pragma unroll
                    for (int c = 0; c < 8; c++)
                        acc[r][c] += ar[r] * br[c];
            }
        }

        // per-thread argmin over its 8 codes, then cross-thread reduce
#pragma unroll
        for (int r = 0; r < 4; r++) {
            int row = ty * 4 + r;
            float s = s_sm[row];
            float bd = 3.4e38f;
            int   bi = 0;
#pragma unroll
            for (int c = 0; c < 8; c++) {
                float t = acc[r][c];
                float d1 = s - 2.0f * t;            // 2*t exact; single rounding
                float dist = d1 + cn_sm[tx * 8 + c]; // second rounding (matches ref)
                if (dist < bd) { bd = dist; bi = kt + tx * 8 + c; }
            }
            red_d[row * 16 + tx] = bd;
            red_i[row * 16 + tx] = bi;
        }
        __syncthreads();
        if (tx == 0) {
#pragma unroll
            for (int r = 0; r < 4; r++) {
                int row = ty * 4 + r;
                float bd = best_d[row];
                int   bi = best_i[row];
#pragma unroll
                for (int j = 0; j < 16; j++) {       // ascending k order
                    float d = red_d[row * 16 + j];
                    if (d < bd) { bd = d; bi = red_i[row * 16 + j]; }
                }
                best_d[row] = bd;
                best_i[row] = bi;
            }
        }
        __syncthreads();
    }

    if (tid < BM) g_idx[row0 + tid] = best_i[tid];
}

// ---------------------------------------------------------------------------
// Kernel 3: gather z_q, write straight-through output
//   out = fp32(z_e + fp32(z_q - z_e))  (replicates reference rounding),
// and accumulate sum of (z_q - z_e)^2 in fp64 for the losses.
// ---------------------------------------------------------------------------
__global__ void gather_loss_kernel(const float* __restrict__ x,
                                   const float* __restrict__ cb,
                                   float* __restrict__ out) {
    __shared__ double part[256];
    double lsum = 0.0;
    const size_t total = (size_t)N_ROWS * DDIM;
    for (size_t e = (size_t)blockIdx.x * blockDim.x + threadIdx.x;
         e < total; e += (size_t)gridDim.x * blockDim.x) {
        int n = (int)(e >> 9);         // e / 512
        int d = (int)(e & 511);        // e % 512
        int k = g_idx[n];
        float zq = cb[(size_t)k * DDIM + d];
        float ze = x[e];
        float diff = zq - ze;
        out[e] = ze + diff;            // straight-through forward
        lsum += (double)diff * (double)diff;
    }
    part[threadIdx.x] = lsum;
    __syncthreads();
    for (int s = 128; s; s >>= 1) {
        if (threadIdx.x < s) part[threadIdx.x] += part[threadIdx.x + s];
        __syncthreads();
    }
    if (threadIdx.x == 0) atomicAdd(&g_loss, part[0]);
}

// ---------------------------------------------------------------------------
// Kernel 4: write losses + indices (layout-defensive via out_size guard)
// ---------------------------------------------------------------------------
__global__ void finalize_kernel(float* __restrict__ out, long long out_size) {
    const long long base = (long long)N_ROWS * DDIM;
    if (blockIdx.x == 0 && threadIdx.x == 0 && out_size >= base + 2) {
        float loss = (float)(g_loss / ((double)N_ROWS * (double)DDIM));
        out[base]     = loss;  // vq_loss
        out[base + 1] = loss;  // commit_loss (identical forward value)
    }
    if (out_size >= base + 2 + N_ROWS) {
        for (int n = blockIdx.x * blockDim.x + threadIdx.x; n < N_ROWS;
             n += gridDim.x * blockDim.x)
            out[base + 2 + n] = (float)g_idx[n];
    }
}

// ---------------------------------------------------------------------------
extern "C" void kernel_launch(void* const* d_in, const int* in_sizes, int n_in,
                              void* d_out, int out_size) {
    const float* x  = (const float*)d_in[0];
    const float* cb = (const float*)d_in[1];
    float* out = (float*)d_out;

    // 1) norms (24576 warps -> 3072 blocks of 256)
    rownorm_kernel<<<(N_ROWS + K_CODES) / 8, 256>>>(x, cb);

    // 2) fused GEMM + argmin
    vq_argmin_kernel<<<N_ROWS / BM, 256>>>(x, cb);

    // 3) gather + ST output + loss
    gather_loss_kernel<<<2048, 256>>>(x, cb, out);

    // 4) losses + indices
    finalize_kernel<<<64, 256>>>(out, (long long)out_size);
}